// round 1
// baseline (speedup 1.0000x reference)
#include <cuda_runtime.h>
#include <math.h>

// ---------------- problem constants ----------------
#define DIMN     1024
#define HEADS    16
#define HEAD_DIM 64
#define LAYERS   4
#define HIDDEN   4096
#define VOCAB    32000
#define BATCH    2
#define SEQ      1024
#define MTOK     (BATCH*SEQ)          // 2048 tokens
#define EPS      1e-6f

// ---------------- scratch (device globals; no runtime alloc allowed) ------
__device__ float g_h   [MTOK*DIMN];
__device__ float g_x   [MTOK*DIMN];
__device__ float g_q   [MTOK*DIMN];
__device__ float g_k   [MTOK*DIMN];
__device__ float g_v   [MTOK*DIMN];
__device__ float g_y   [MTOK*DIMN];
__device__ float g_att [(size_t)BATCH*HEADS*SEQ*SEQ];   // 134 MB
__device__ float g_gate[MTOK*HIDDEN];
__device__ float g_up  [MTOK*HIDDEN];

// ---------------- embed gather ----------------
__global__ void embed_kernel(const int* __restrict__ tokens,
                             const float* __restrict__ embed,
                             float* __restrict__ h)
{
    int row = blockIdx.x;                 // 0..MTOK-1
    int tok = tokens[row];
    const float4* src = (const float4*)(embed + (long)tok * DIMN);
    float4*       dst = (float4*)(h + (long)row * DIMN);
    dst[threadIdx.x] = src[threadIdx.x];  // 256 threads * 4 = 1024
}

// ---------------- rmsnorm (one block per token row, D=1024) ----------------
__global__ void rmsnorm_kernel(const float* __restrict__ x,
                               const float* __restrict__ w,
                               float* __restrict__ out)
{
    int row = blockIdx.x;
    const float4* xr = (const float4*)(x + (long)row * DIMN);
    float4 v = xr[threadIdx.x];
    float ss = v.x*v.x + v.y*v.y + v.z*v.z + v.w*v.w;

    __shared__ float red[8];
    #pragma unroll
    for (int o = 16; o > 0; o >>= 1) ss += __shfl_xor_sync(0xFFFFFFFFu, ss, o);
    if ((threadIdx.x & 31) == 0) red[threadIdx.x >> 5] = ss;
    __syncthreads();
    if (threadIdx.x < 8) {
        float s = red[threadIdx.x];
        #pragma unroll
        for (int o = 4; o > 0; o >>= 1) s += __shfl_xor_sync(0xFFu, s, o);
        if (threadIdx.x == 0) red[0] = s;
    }
    __syncthreads();
    float scale = rsqrtf(red[0] * (1.0f / DIMN) + EPS);

    float4 wv = ((const float4*)w)[threadIdx.x];
    float4 o4;
    o4.x = v.x * scale * wv.x;
    o4.y = v.y * scale * wv.y;
    o4.z = v.z * scale * wv.z;
    o4.w = v.w * scale * wv.w;
    ((float4*)(out + (long)row * DIMN))[threadIdx.x] = o4;
}

// ---------------- row softmax over SEQ=1024 ----------------
__global__ void softmax_kernel(float* __restrict__ att)
{
    long row = blockIdx.x;
    float4* p = (float4*)(att + row * (long)SEQ);
    float4 v = p[threadIdx.x];

    __shared__ float red[8];
    float mx = fmaxf(fmaxf(v.x, v.y), fmaxf(v.z, v.w));
    #pragma unroll
    for (int o = 16; o > 0; o >>= 1) mx = fmaxf(mx, __shfl_xor_sync(0xFFFFFFFFu, mx, o));
    if ((threadIdx.x & 31) == 0) red[threadIdx.x >> 5] = mx;
    __syncthreads();
    if (threadIdx.x < 8) {
        float s = red[threadIdx.x];
        #pragma unroll
        for (int o = 4; o > 0; o >>= 1) s = fmaxf(s, __shfl_xor_sync(0xFFu, s, o));
        if (threadIdx.x == 0) red[0] = s;
    }
    __syncthreads();
    mx = red[0];
    __syncthreads();

    v.x = expf(v.x - mx); v.y = expf(v.y - mx);
    v.z = expf(v.z - mx); v.w = expf(v.w - mx);
    float sum = v.x + v.y + v.z + v.w;
    #pragma unroll
    for (int o = 16; o > 0; o >>= 1) sum += __shfl_xor_sync(0xFFFFFFFFu, sum, o);
    if ((threadIdx.x & 31) == 0) red[threadIdx.x >> 5] = sum;
    __syncthreads();
    if (threadIdx.x < 8) {
        float s = red[threadIdx.x];
        #pragma unroll
        for (int o = 4; o > 0; o >>= 1) s += __shfl_xor_sync(0xFFu, s, o);
        if (threadIdx.x == 0) red[0] = s;
    }
    __syncthreads();
    float inv = 1.0f / red[0];
    v.x *= inv; v.y *= inv; v.z *= inv; v.w *= inv;
    p[threadIdx.x] = v;
}

// ---------------- silu(gate) * up, in place into gate ----------------
__global__ void silu_mul_kernel(float4* __restrict__ g, const float4* __restrict__ u)
{
    long i = (long)blockIdx.x * blockDim.x + threadIdx.x;
    float4 gv = g[i], uv = u[i];
    gv.x = gv.x / (1.0f + expf(-gv.x)) * uv.x;
    gv.y = gv.y / (1.0f + expf(-gv.y)) * uv.y;
    gv.z = gv.z / (1.0f + expf(-gv.z)) * uv.z;
    gv.w = gv.w / (1.0f + expf(-gv.w)) * uv.w;
    g[i] = gv;
}

// ---------------- tiled GEMM: C = alpha * A * op(B) [+ C] -----------------
// TRANS_B=true : C[m,n] = sum_k A[m,k]*B[n,k]   (B row-major [N,K], k-contig)
// TRANS_B=false: C[m,n] = sum_k A[m,k]*B[k,n]   (B row-major [K,N], n-contig)
// Batched over blockIdx.z; z decomposed as (bb = z/hdiv, hh = z%hdiv),
// pointer offset = bb*s?b + hh*s?h. All dims must be multiples of tile sizes
// (they are, for every call in this problem).
#define BM 64
#define BN 64
#define BK 16

template<bool ACCUM, bool TRANS_B>
__global__ void __launch_bounds__(256)
gemm_kernel(const float* __restrict__ A, int lda, long sAb, long sAh,
            const float* __restrict__ B, int ldb, long sBb, long sBh,
            float*       __restrict__ C, int ldc, long sCb, long sCh,
            int M, int N, int K, float alpha, int hdiv)
{
    int z  = blockIdx.z;
    int bb = z / hdiv, hh = z % hdiv;
    A += bb * sAb + hh * sAh;
    B += bb * sBb + hh * sBh;
    C += bb * sCb + hh * sCh;

    int m0 = blockIdx.y * BM;
    int n0 = blockIdx.x * BN;

    __shared__ float As[BK][BM];
    __shared__ float Bs[BK][BN];

    int tid = threadIdx.x;          // 0..255
    int tx  = tid & 15;             // n quad
    int ty  = tid >> 4;             // m quad

    // load-index precompute
    int lr = tid >> 2;              // 0..63  (row within 64-tile for NT loads)
    int lk = (tid & 3) << 2;        // 0,4,8,12 (k offset for NT loads)
    int br = tid >> 4;              // 0..15  (k row for NN B load)
    int bc = (tid & 15) << 2;       // 0..60  (n offset for NN B load)

    float acc[4][4] = {};

    for (int k0 = 0; k0 < K; k0 += BK) {
        // A tile (always [M,K] k-contig) -> transposed into As[k][m]
        float4 a4 = *(const float4*)&A[(long)(m0 + lr) * lda + k0 + lk];
        As[lk + 0][lr] = a4.x; As[lk + 1][lr] = a4.y;
        As[lk + 2][lr] = a4.z; As[lk + 3][lr] = a4.w;

        if (TRANS_B) {
            float4 b4 = *(const float4*)&B[(long)(n0 + lr) * ldb + k0 + lk];
            Bs[lk + 0][lr] = b4.x; Bs[lk + 1][lr] = b4.y;
            Bs[lk + 2][lr] = b4.z; Bs[lk + 3][lr] = b4.w;
        } else {
            float4 b4 = *(const float4*)&B[(long)(k0 + br) * ldb + n0 + bc];
            *(float4*)&Bs[br][bc] = b4;
        }
        __syncthreads();

        #pragma unroll
        for (int kk = 0; kk < BK; kk++) {
            float a0 = As[kk][ty * 4 + 0], a1 = As[kk][ty * 4 + 1];
            float a2 = As[kk][ty * 4 + 2], a3 = As[kk][ty * 4 + 3];
            float b0 = Bs[kk][tx * 4 + 0], b1 = Bs[kk][tx * 4 + 1];
            float b2 = Bs[kk][tx * 4 + 2], b3 = Bs[kk][tx * 4 + 3];
            acc[0][0] += a0 * b0; acc[0][1] += a0 * b1; acc[0][2] += a0 * b2; acc[0][3] += a0 * b3;
            acc[1][0] += a1 * b0; acc[1][1] += a1 * b1; acc[1][2] += a1 * b2; acc[1][3] += a1 * b3;
            acc[2][0] += a2 * b0; acc[2][1] += a2 * b1; acc[2][2] += a2 * b2; acc[2][3] += a2 * b3;
            acc[3][0] += a3 * b0; acc[3][1] += a3 * b1; acc[3][2] += a3 * b2; acc[3][3] += a3 * b3;
        }
        __syncthreads();
    }

    #pragma unroll
    for (int i = 0; i < 4; i++) {
        long idx = (long)(m0 + ty * 4 + i) * ldc + n0 + tx * 4;
        float4 c4;
        c4.x = alpha * acc[i][0]; c4.y = alpha * acc[i][1];
        c4.z = alpha * acc[i][2]; c4.w = alpha * acc[i][3];
        if (ACCUM) {
            float4 old = *(float4*)&C[idx];
            c4.x += old.x; c4.y += old.y; c4.z += old.z; c4.w += old.w;
        }
        *(float4*)&C[idx] = c4;
    }
}

// ---------------- launcher ----------------
extern "C" void kernel_launch(void* const* d_in, const int* in_sizes, int n_in,
                              void* d_out, int out_size)
{
    const int*   tokens  = (const int*)  d_in[0];
    const float* embed   = (const float*)d_in[1];
    const float* Wq      = (const float*)d_in[2];
    const float* Wk      = (const float*)d_in[3];
    const float* Wv      = (const float*)d_in[4];
    const float* Wo      = (const float*)d_in[5];
    const float* Wg      = (const float*)d_in[6];
    const float* Wu      = (const float*)d_in[7];
    const float* Wd      = (const float*)d_in[8];
    const float* ln1     = (const float*)d_in[9];
    const float* ln2     = (const float*)d_in[10];
    const float* norm_w  = (const float*)d_in[11];
    const float* lm_head = (const float*)d_in[12];
    float* out = (float*)d_out;

    float *h, *x, *q, *k, *v, *y, *att, *gate, *up;
    cudaGetSymbolAddress((void**)&h,    g_h);
    cudaGetSymbolAddress((void**)&x,    g_x);
    cudaGetSymbolAddress((void**)&q,    g_q);
    cudaGetSymbolAddress((void**)&k,    g_k);
    cudaGetSymbolAddress((void**)&v,    g_v);
    cudaGetSymbolAddress((void**)&y,    g_y);
    cudaGetSymbolAddress((void**)&att,  g_att);
    cudaGetSymbolAddress((void**)&gate, g_gate);
    cudaGetSymbolAddress((void**)&up,   g_up);

    const float scale = 1.0f / sqrtf((float)HEAD_DIM);

    embed_kernel<<<MTOK, 256>>>(tokens, embed, h);

    dim3 gProj(DIMN / BN,   MTOK / BM, 1);          // 16 x 32
    dim3 gFfn (HIDDEN / BN, MTOK / BM, 1);          // 64 x 32
    dim3 gDown(DIMN / BN,   MTOK / BM, 1);
    dim3 gScore(SEQ / BN, SEQ / BM, BATCH * HEADS); // 16 x 16 x 32
    dim3 gAV  (HEAD_DIM / BN, SEQ / BM, BATCH * HEADS); // 1 x 16 x 32
    dim3 gHead(VOCAB / BN, MTOK / BM, 1);           // 500 x 32

    for (int l = 0; l < LAYERS; l++) {
        const float* wq = Wq + (long)l * DIMN * DIMN;
        const float* wk = Wk + (long)l * DIMN * DIMN;
        const float* wv = Wv + (long)l * DIMN * DIMN;
        const float* wo = Wo + (long)l * DIMN * DIMN;
        const float* wg = Wg + (long)l * HIDDEN * DIMN;
        const float* wu = Wu + (long)l * HIDDEN * DIMN;
        const float* wd = Wd + (long)l * DIMN * HIDDEN;

        // x = rmsnorm(h, ln1[l])
        rmsnorm_kernel<<<MTOK, 256>>>(h, ln1 + (long)l * DIMN, x);

        // q,k,v = x @ W^T
        gemm_kernel<false, true><<<gProj, 256>>>(x, DIMN, 0, 0, wq, DIMN, 0, 0,
                                                 q, DIMN, 0, 0, MTOK, DIMN, DIMN, 1.0f, 1);
        gemm_kernel<false, true><<<gProj, 256>>>(x, DIMN, 0, 0, wk, DIMN, 0, 0,
                                                 k, DIMN, 0, 0, MTOK, DIMN, DIMN, 1.0f, 1);
        gemm_kernel<false, true><<<gProj, 256>>>(x, DIMN, 0, 0, wv, DIMN, 0, 0,
                                                 v, DIMN, 0, 0, MTOK, DIMN, DIMN, 1.0f, 1);

        // att[b,h,t,s] = scale * q . k   (batched NT over b,h)
        gemm_kernel<false, true><<<gScore, 256>>>(
            q, DIMN, (long)SEQ * DIMN, HEAD_DIM,
            k, DIMN, (long)SEQ * DIMN, HEAD_DIM,
            att, SEQ, (long)HEADS * SEQ * SEQ, (long)SEQ * SEQ,
            SEQ, SEQ, HEAD_DIM, scale, HEADS);

        softmax_kernel<<<BATCH * HEADS * SEQ, 256>>>(att);

        // y = att @ v  (batched NN over b,h)
        gemm_kernel<false, false><<<gAV, 256>>>(
            att, SEQ, (long)HEADS * SEQ * SEQ, (long)SEQ * SEQ,
            v, DIMN, (long)SEQ * DIMN, HEAD_DIM,
            y, DIMN, (long)SEQ * DIMN, HEAD_DIM,
            SEQ, HEAD_DIM, SEQ, 1.0f, HEADS);

        // h += y @ Wo^T
        gemm_kernel<true, true><<<gProj, 256>>>(y, DIMN, 0, 0, wo, DIMN, 0, 0,
                                                h, DIMN, 0, 0, MTOK, DIMN, DIMN, 1.0f, 1);

        // x = rmsnorm(h, ln2[l])
        rmsnorm_kernel<<<MTOK, 256>>>(h, ln2 + (long)l * DIMN, x);

        // gate = x @ Wg^T ; up = x @ Wu^T
        gemm_kernel<false, true><<<gFfn, 256>>>(x, DIMN, 0, 0, wg, DIMN, 0, 0,
                                                gate, HIDDEN, 0, 0, MTOK, HIDDEN, DIMN, 1.0f, 1);
        gemm_kernel<false, true><<<gFfn, 256>>>(x, DIMN, 0, 0, wu, DIMN, 0, 0,
                                                up, HIDDEN, 0, 0, MTOK, HIDDEN, DIMN, 1.0f, 1);

        // gate = silu(gate) * up
        silu_mul_kernel<<<(MTOK * (long)HIDDEN / 4) / 256, 256>>>((float4*)gate, (const float4*)up);

        // h += gate @ Wd^T
        gemm_kernel<true, true><<<gDown, 256>>>(gate, HIDDEN, 0, 0, wd, HIDDEN, 0, 0,
                                                h, DIMN, 0, 0, MTOK, DIMN, HIDDEN, 1.0f, 1);
    }

    // out = rmsnorm(h, norm_w) @ lm_head^T
    rmsnorm_kernel<<<MTOK, 256>>>(h, norm_w, x);
    gemm_kernel<false, true><<<gHead, 256>>>(x, DIMN, 0, 0, lm_head, DIMN, 0, 0,
                                             out, VOCAB, 0, 0, MTOK, VOCAB, DIMN, 1.0f, 1);
}

// round 2
// speedup vs baseline: 1.4788x; 1.4788x over previous
#include <cuda_runtime.h>
#include <math.h>

// ---------------- problem constants ----------------
#define DIMN     1024
#define HEADS    16
#define HEAD_DIM 64
#define LAYERS   4
#define HIDDEN   4096
#define VOCAB    32000
#define BATCH    2
#define SEQ      1024
#define MTOK     (BATCH*SEQ)          // 2048 tokens
#define EPS      1e-6f

// ---------------- scratch (device globals; no runtime alloc allowed) ------
__device__ float g_h   [MTOK*DIMN];
__device__ float g_x   [MTOK*DIMN];
__device__ float g_q   [MTOK*DIMN];
__device__ float g_k   [MTOK*DIMN];
__device__ float g_v   [MTOK*DIMN];
__device__ float g_y   [MTOK*DIMN];
__device__ float g_att [(size_t)BATCH*HEADS*SEQ*SEQ];   // 134 MB
__device__ float g_gate[MTOK*HIDDEN];
__device__ float g_up  [MTOK*HIDDEN];

// ---------------- embed gather ----------------
__global__ void embed_kernel(const int* __restrict__ tokens,
                             const float* __restrict__ embed,
                             float* __restrict__ h)
{
    int row = blockIdx.x;
    int tok = tokens[row];
    const float4* src = (const float4*)(embed + (long)tok * DIMN);
    float4*       dst = (float4*)(h + (long)row * DIMN);
    dst[threadIdx.x] = src[threadIdx.x];
}

// ---------------- rmsnorm (one block per token row, D=1024) ----------------
__global__ void rmsnorm_kernel(const float* __restrict__ x,
                               const float* __restrict__ w,
                               float* __restrict__ out)
{
    int row = blockIdx.x;
    const float4* xr = (const float4*)(x + (long)row * DIMN);
    float4 v = xr[threadIdx.x];
    float ss = v.x*v.x + v.y*v.y + v.z*v.z + v.w*v.w;

    __shared__ float red[8];
    #pragma unroll
    for (int o = 16; o > 0; o >>= 1) ss += __shfl_xor_sync(0xFFFFFFFFu, ss, o);
    if ((threadIdx.x & 31) == 0) red[threadIdx.x >> 5] = ss;
    __syncthreads();
    if (threadIdx.x < 8) {
        float s = red[threadIdx.x];
        #pragma unroll
        for (int o = 4; o > 0; o >>= 1) s += __shfl_xor_sync(0xFFu, s, o);
        if (threadIdx.x == 0) red[0] = s;
    }
    __syncthreads();
    float scale = rsqrtf(red[0] * (1.0f / DIMN) + EPS);

    float4 wv = ((const float4*)w)[threadIdx.x];
    float4 o4;
    o4.x = v.x * scale * wv.x;
    o4.y = v.y * scale * wv.y;
    o4.z = v.z * scale * wv.z;
    o4.w = v.w * scale * wv.w;
    ((float4*)(out + (long)row * DIMN))[threadIdx.x] = o4;
}

// ---------------- row softmax over SEQ=1024 ----------------
__global__ void softmax_kernel(float* __restrict__ att)
{
    long row = blockIdx.x;
    float4* p = (float4*)(att + row * (long)SEQ);
    float4 v = p[threadIdx.x];

    __shared__ float red[8];
    float mx = fmaxf(fmaxf(v.x, v.y), fmaxf(v.z, v.w));
    #pragma unroll
    for (int o = 16; o > 0; o >>= 1) mx = fmaxf(mx, __shfl_xor_sync(0xFFFFFFFFu, mx, o));
    if ((threadIdx.x & 31) == 0) red[threadIdx.x >> 5] = mx;
    __syncthreads();
    if (threadIdx.x < 8) {
        float s = red[threadIdx.x];
        #pragma unroll
        for (int o = 4; o > 0; o >>= 1) s = fmaxf(s, __shfl_xor_sync(0xFFu, s, o));
        if (threadIdx.x == 0) red[0] = s;
    }
    __syncthreads();
    mx = red[0];
    __syncthreads();

    v.x = expf(v.x - mx); v.y = expf(v.y - mx);
    v.z = expf(v.z - mx); v.w = expf(v.w - mx);
    float sum = v.x + v.y + v.z + v.w;
    #pragma unroll
    for (int o = 16; o > 0; o >>= 1) sum += __shfl_xor_sync(0xFFFFFFFFu, sum, o);
    if ((threadIdx.x & 31) == 0) red[threadIdx.x >> 5] = sum;
    __syncthreads();
    if (threadIdx.x < 8) {
        float s = red[threadIdx.x];
        #pragma unroll
        for (int o = 4; o > 0; o >>= 1) s += __shfl_xor_sync(0xFFu, s, o);
        if (threadIdx.x == 0) red[0] = s;
    }
    __syncthreads();
    float inv = 1.0f / red[0];
    v.x *= inv; v.y *= inv; v.z *= inv; v.w *= inv;
    p[threadIdx.x] = v;
}

// ---------------- silu(gate) * up, in place into gate ----------------
__global__ void silu_mul_kernel(float4* __restrict__ g, const float4* __restrict__ u)
{
    long i = (long)blockIdx.x * blockDim.x + threadIdx.x;
    float4 gv = g[i], uv = u[i];
    gv.x = gv.x / (1.0f + expf(-gv.x)) * uv.x;
    gv.y = gv.y / (1.0f + expf(-gv.y)) * uv.y;
    gv.z = gv.z / (1.0f + expf(-gv.z)) * uv.z;
    gv.w = gv.w / (1.0f + expf(-gv.w)) * uv.w;
    g[i] = gv;
}

// ================= high-throughput SGEMM =================
// C = alpha * A * op(B) [+ C]
// A is row-major [M,K] (k-contig). TRANS_B: B row-major [N,K]; else [K,N].
// Tiles: BM x BN x 16, 256 threads, microtile (BM/16) x (BN/16) per thread,
// double-buffered smem, register-staged prefetch.
// All dims must divide evenly (they do for every call here).
template<int BM, int BN, bool ACCUM, bool TRANS_B>
__global__ void __launch_bounds__(256, 2)
gemm2(const float* __restrict__ A, int lda, long sAb, long sAh,
      const float* __restrict__ B, int ldb, long sBb, long sBh,
      float*       __restrict__ C, int ldc, long sCb, long sCh,
      int K, float alpha, int hdiv)
{
    constexpr int BK = 16;
    constexpr int RM = BM / 64;           // row groups (4 rows each)
    constexpr int CN = BN / 64;           // col groups
    constexpr int LA = BM / 64;           // float4 A-loads per thread
    constexpr int LB = BN / 64;           // float4 B-loads per thread

    __shared__ float As[2][BK][BM + 4];
    __shared__ float Bs[2][BK][BN + 4];

    const int tid = threadIdx.x;
    const int tx  = tid & 15;
    const int ty  = tid >> 4;

    const int z = blockIdx.z;
    A += (z / hdiv) * sAb + (z % hdiv) * sAh;
    B += (z / hdiv) * sBb + (z % hdiv) * sBh;
    C += (z / hdiv) * sCb + (z % hdiv) * sCh;

    const int m0 = blockIdx.y * BM;
    const int n0 = blockIdx.x * BN;

    // load-index precompute (k-contig pattern: r = idx>>2, kq = (idx&3)*4)
    int ar[LA], ak[LA];
    #pragma unroll
    for (int i = 0; i < LA; i++) {
        int idx = tid + i * 256;
        ar[i] = idx >> 2;
        ak[i] = (idx & 3) << 2;
    }
    int bR[LB], bK[LB];   // TRANS: row-in-tile, k-offset.  NN: c-offset, k-row.
    #pragma unroll
    for (int i = 0; i < LB; i++) {
        int idx = tid + i * 256;
        if (TRANS_B) { bR[i] = idx >> 2;               bK[i] = (idx & 3) << 2; }
        else         { bR[i] = (idx % (BN / 4)) << 2;  bK[i] = idx / (BN / 4); }
    }

    float4 pa[LA], pb[LB];
    auto load_g = [&](int k0) {
        #pragma unroll
        for (int i = 0; i < LA; i++)
            pa[i] = *(const float4*)&A[(long)(m0 + ar[i]) * lda + k0 + ak[i]];
        #pragma unroll
        for (int i = 0; i < LB; i++) {
            if (TRANS_B)
                pb[i] = *(const float4*)&B[(long)(n0 + bR[i]) * ldb + k0 + bK[i]];
            else
                pb[i] = *(const float4*)&B[(long)(k0 + bK[i]) * ldb + n0 + bR[i]];
        }
    };
    auto store_s = [&](int s) {
        #pragma unroll
        for (int i = 0; i < LA; i++) {
            As[s][ak[i] + 0][ar[i]] = pa[i].x;
            As[s][ak[i] + 1][ar[i]] = pa[i].y;
            As[s][ak[i] + 2][ar[i]] = pa[i].z;
            As[s][ak[i] + 3][ar[i]] = pa[i].w;
        }
        #pragma unroll
        for (int i = 0; i < LB; i++) {
            if (TRANS_B) {
                Bs[s][bK[i] + 0][bR[i]] = pb[i].x;
                Bs[s][bK[i] + 1][bR[i]] = pb[i].y;
                Bs[s][bK[i] + 2][bR[i]] = pb[i].z;
                Bs[s][bK[i] + 3][bR[i]] = pb[i].w;
            } else {
                *(float4*)&Bs[s][bK[i]][bR[i]] = pb[i];
            }
        }
    };

    float acc[RM * 4][CN * 4];
    #pragma unroll
    for (int i = 0; i < RM * 4; i++)
        #pragma unroll
        for (int j = 0; j < CN * 4; j++) acc[i][j] = 0.0f;

    load_g(0);
    store_s(0);
    __syncthreads();

    const int nk = K / BK;
    for (int t = 0; t < nk; t++) {
        const int buf = t & 1;
        if (t + 1 < nk) load_g((t + 1) * BK);

        #pragma unroll
        for (int kk = 0; kk < BK; kk++) {
            float4 af4[RM], bf4[CN];
            #pragma unroll
            for (int g = 0; g < RM; g++)
                af4[g] = *(const float4*)&As[buf][kk][g * 64 + ty * 4];
            #pragma unroll
            for (int c = 0; c < CN; c++)
                bf4[c] = *(const float4*)&Bs[buf][kk][c * 64 + tx * 4];
            const float* af = (const float*)af4;
            const float* bf = (const float*)bf4;
            #pragma unroll
            for (int i = 0; i < RM * 4; i++)
                #pragma unroll
                for (int j = 0; j < CN * 4; j++)
                    acc[i][j] += af[i] * bf[j];
        }

        if (t + 1 < nk) store_s(buf ^ 1);
        __syncthreads();
    }

    #pragma unroll
    for (int g = 0; g < RM; g++) {
        #pragma unroll
        for (int i = 0; i < 4; i++) {
            long row = m0 + g * 64 + ty * 4 + i;
            #pragma unroll
            for (int c = 0; c < CN; c++) {
                long idx = row * (long)ldc + n0 + c * 64 + tx * 4;
                float4 r;
                r.x = alpha * acc[g * 4 + i][c * 4 + 0];
                r.y = alpha * acc[g * 4 + i][c * 4 + 1];
                r.z = alpha * acc[g * 4 + i][c * 4 + 2];
                r.w = alpha * acc[g * 4 + i][c * 4 + 3];
                if (ACCUM) {
                    float4 old = *(float4*)&C[idx];
                    r.x += old.x; r.y += old.y; r.z += old.z; r.w += old.w;
                }
                *(float4*)&C[idx] = r;
            }
        }
    }
}

// ---------------- launcher ----------------
extern "C" void kernel_launch(void* const* d_in, const int* in_sizes, int n_in,
                              void* d_out, int out_size)
{
    const int*   tokens  = (const int*)  d_in[0];
    const float* embed   = (const float*)d_in[1];
    const float* Wq      = (const float*)d_in[2];
    const float* Wk      = (const float*)d_in[3];
    const float* Wv      = (const float*)d_in[4];
    const float* Wo      = (const float*)d_in[5];
    const float* Wg      = (const float*)d_in[6];
    const float* Wu      = (const float*)d_in[7];
    const float* Wd      = (const float*)d_in[8];
    const float* ln1     = (const float*)d_in[9];
    const float* ln2     = (const float*)d_in[10];
    const float* norm_w  = (const float*)d_in[11];
    const float* lm_head = (const float*)d_in[12];
    float* out = (float*)d_out;

    float *h, *x, *q, *k, *v, *y, *att, *gate, *up;
    cudaGetSymbolAddress((void**)&h,    g_h);
    cudaGetSymbolAddress((void**)&x,    g_x);
    cudaGetSymbolAddress((void**)&q,    g_q);
    cudaGetSymbolAddress((void**)&k,    g_k);
    cudaGetSymbolAddress((void**)&v,    g_v);
    cudaGetSymbolAddress((void**)&y,    g_y);
    cudaGetSymbolAddress((void**)&att,  g_att);
    cudaGetSymbolAddress((void**)&gate, g_gate);
    cudaGetSymbolAddress((void**)&up,   g_up);

    const float scale = 1.0f / sqrtf((float)HEAD_DIM);

    embed_kernel<<<MTOK, 256>>>(tokens, embed, h);

    dim3 gProj (DIMN / 64,    MTOK / 128, 1);             // 16 x 16
    dim3 gFfn  (HIDDEN / 128, MTOK / 128, 1);             // 32 x 16
    dim3 gDown (DIMN / 64,    MTOK / 128, 1);             // 16 x 16
    dim3 gScore(SEQ / 128, SEQ / 128, BATCH * HEADS);     // 8 x 8 x 32
    dim3 gAV   (HEAD_DIM / 64, SEQ / 128, BATCH * HEADS); // 1 x 8 x 32
    dim3 gHead (VOCAB / 128,  MTOK / 128, 1);             // 250 x 16

    for (int l = 0; l < LAYERS; l++) {
        const float* wq = Wq + (long)l * DIMN * DIMN;
        const float* wk = Wk + (long)l * DIMN * DIMN;
        const float* wv = Wv + (long)l * DIMN * DIMN;
        const float* wo = Wo + (long)l * DIMN * DIMN;
        const float* wg = Wg + (long)l * HIDDEN * DIMN;
        const float* wu = Wu + (long)l * HIDDEN * DIMN;
        const float* wd = Wd + (long)l * DIMN * HIDDEN;

        rmsnorm_kernel<<<MTOK, 256>>>(h, ln1 + (long)l * DIMN, x);

        gemm2<128,  64, false, true><<<gProj, 256>>>(x, DIMN, 0, 0, wq, DIMN, 0, 0,
                                                     q, DIMN, 0, 0, DIMN, 1.0f, 1);
        gemm2<128,  64, false, true><<<gProj, 256>>>(x, DIMN, 0, 0, wk, DIMN, 0, 0,
                                                     k, DIMN, 0, 0, DIMN, 1.0f, 1);
        gemm2<128,  64, false, true><<<gProj, 256>>>(x, DIMN, 0, 0, wv, DIMN, 0, 0,
                                                     v, DIMN, 0, 0, DIMN, 1.0f, 1);

        // att[b,h,t,s] = scale * q . k   (batched NT over b,h)
        gemm2<128, 128, false, true><<<gScore, 256>>>(
            q, DIMN, (long)SEQ * DIMN, HEAD_DIM,
            k, DIMN, (long)SEQ * DIMN, HEAD_DIM,
            att, SEQ, (long)HEADS * SEQ * SEQ, (long)SEQ * SEQ,
            HEAD_DIM, scale, HEADS);

        softmax_kernel<<<BATCH * HEADS * SEQ, 256>>>(att);

        // y = att @ v  (batched NN over b,h)
        gemm2<128, 64, false, false><<<gAV, 256>>>(
            att, SEQ, (long)HEADS * SEQ * SEQ, (long)SEQ * SEQ,
            v, DIMN, (long)SEQ * DIMN, HEAD_DIM,
            y, DIMN, (long)SEQ * DIMN, HEAD_DIM,
            SEQ, 1.0f, HEADS);

        // h += y @ Wo^T
        gemm2<128, 64, true, true><<<gProj, 256>>>(y, DIMN, 0, 0, wo, DIMN, 0, 0,
                                                   h, DIMN, 0, 0, DIMN, 1.0f, 1);

        rmsnorm_kernel<<<MTOK, 256>>>(h, ln2 + (long)l * DIMN, x);

        gemm2<128, 128, false, true><<<gFfn, 256>>>(x, DIMN, 0, 0, wg, DIMN, 0, 0,
                                                    gate, HIDDEN, 0, 0, DIMN, 1.0f, 1);
        gemm2<128, 128, false, true><<<gFfn, 256>>>(x, DIMN, 0, 0, wu, DIMN, 0, 0,
                                                    up, HIDDEN, 0, 0, DIMN, 1.0f, 1);

        silu_mul_kernel<<<(MTOK * (long)HIDDEN / 4) / 256, 256>>>((float4*)gate, (const float4*)up);

        // h += gate @ Wd^T
        gemm2<128, 64, true, true><<<gDown, 256>>>(gate, HIDDEN, 0, 0, wd, HIDDEN, 0, 0,
                                                   h, DIMN, 0, 0, HIDDEN, 1.0f, 1);
    }

    rmsnorm_kernel<<<MTOK, 256>>>(h, norm_w, x);
    gemm2<128, 128, false, true><<<gHead, 256>>>(x, DIMN, 0, 0, lm_head, DIMN, 0, 0,
                                                 out, VOCAB, 0, 0, DIMN, 1.0f, 1);
}

// round 4
// speedup vs baseline: 3.3482x; 2.2641x over previous
#include <cuda_runtime.h>
#include <math.h>
#include <stdint.h>

// ---------------- problem constants ----------------
#define DIMN     1024
#define HEADS    16
#define HEAD_DIM 64
#define LAYERS   4
#define HIDDEN   4096
#define VOCAB    32000
#define BATCH    2
#define SEQ      1024
#define MTOK     (BATCH*SEQ)
#define EPS      1e-6f

// ---------------- scratch ----------------
__device__ float g_h   [MTOK*DIMN];
__device__ float g_x   [MTOK*DIMN];
__device__ float g_q   [MTOK*DIMN];
__device__ float g_k   [MTOK*DIMN];
__device__ float g_v   [MTOK*DIMN];
__device__ float g_vt  [MTOK*DIMN];
__device__ float g_y   [MTOK*DIMN];
__device__ float g_att [(size_t)BATCH*HEADS*SEQ*SEQ];
__device__ float g_gate[MTOK*HIDDEN];
__device__ float g_up  [MTOK*HIDDEN];

// ---------------- PTX helpers (sm_80-class: legal on compute_103) ---------
__device__ __forceinline__ uint32_t smem_u32(const void* p) {
    uint32_t a;
    asm("{ .reg .u64 t; cvta.to.shared.u64 t, %1; cvt.u32.u64 %0, t; }"
        : "=r"(a) : "l"(p));
    return a;
}

__device__ __forceinline__ void ldm4(uint32_t* r, uint32_t addr) {
    asm volatile("ldmatrix.sync.aligned.m8n8.x4.shared.b16 {%0,%1,%2,%3}, [%4];"
                 : "=r"(r[0]), "=r"(r[1]), "=r"(r[2]), "=r"(r[3]) : "r"(addr));
}

__device__ __forceinline__ void mma16816(float* c, const uint32_t* a, const uint32_t* b) {
    asm volatile("mma.sync.aligned.m16n8k16.row.col.f32.bf16.bf16.f32 "
                 "{%0,%1,%2,%3}, {%4,%5,%6,%7}, {%8,%9}, {%0,%1,%2,%3};"
                 : "+f"(c[0]), "+f"(c[1]), "+f"(c[2]), "+f"(c[3])
                 : "r"(a[0]), "r"(a[1]), "r"(a[2]), "r"(a[3]),
                   "r"(b[0]), "r"(b[1]));
}

// fp32 float4 -> hi/lo bf16 quads, stored to swizzled smem.
// hi = truncate-to-bf16 (exact complement in lo); lo truncated again.
// Residual ~2^-16 relative per element.
__device__ __forceinline__ void split_store(uint32_t hi_base, uint32_t lo_base,
                                            int row, int k4, float4 f) {
    uint32_t ux = __float_as_uint(f.x), uy = __float_as_uint(f.y);
    uint32_t uz = __float_as_uint(f.z), uw = __float_as_uint(f.w);
    uint32_t h01 = __byte_perm(ux, uy, 0x7632);
    uint32_t h23 = __byte_perm(uz, uw, 0x7632);
    float lx = f.x - __uint_as_float(ux & 0xFFFF0000u);
    float ly = f.y - __uint_as_float(uy & 0xFFFF0000u);
    float lz = f.z - __uint_as_float(uz & 0xFFFF0000u);
    float lw = f.w - __uint_as_float(uw & 0xFFFF0000u);
    uint32_t l01 = __byte_perm(__float_as_uint(lx), __float_as_uint(ly), 0x7632);
    uint32_t l23 = __byte_perm(__float_as_uint(lz), __float_as_uint(lw), 0x7632);
    int chunk = k4 >> 1, half = k4 & 1;
    uint32_t off = (uint32_t)(row * 64 + ((chunk ^ ((row >> 1) & 3)) << 4) + half * 8);
    asm volatile("st.shared.v2.b32 [%0], {%1,%2};" :: "r"(hi_base + off), "r"(h01), "r"(h23));
    asm volatile("st.shared.v2.b32 [%0], {%1,%2};" :: "r"(lo_base + off), "r"(l01), "r"(l23));
}

// ================= mma.sync GEMM: C = alpha * A * B^T [+C] ================
// A row-major [M,K] k-contig, B row-major [N,K] k-contig, fp32 in/out.
// CTA tile 128 x BN, BK=32, 256 threads (8 warps, 2m x 4n).
// blockIdx.x = m-tile (fast), blockIdx.y = n-tile, blockIdx.z = batch.
template<int BN, bool ACCUM>
__global__ void __launch_bounds__(256, 1)
mma_gemm(const float* __restrict__ A, int lda, long sAb, long sAh,
         const float* __restrict__ B, int ldb, long sBb, long sBh,
         float*       __restrict__ C, int ldc, long sCb, long sCh,
         int K, float alpha, int hdiv)
{
    constexpr int WN    = BN / 4;           // warp n-tile (32 or 16)
    constexpr int NA    = WN / 8;           // n-atoms per warp (4 or 2)
    constexpr int NB4   = BN / 32;          // B float4 loads per thread
    constexpr int A_LO  = 8192;             // A: 128 rows x 64B
    constexpr int B_HI  = 16384;
    constexpr int BLO_D = BN * 64;          // B_LO - B_HI
    constexpr int STAGE = 16384 + BN * 128;

    extern __shared__ char smem[];
    const uint32_t sb0 = smem_u32(smem);

    const int tid = threadIdx.x, lane = tid & 31, wid = tid >> 5;
    const int wm = wid & 1, wn = wid >> 1;

    const int z = blockIdx.z;
    A += (z / hdiv) * sAb + (z % hdiv) * sAh;
    B += (z / hdiv) * sBb + (z % hdiv) * sBh;
    C += (z / hdiv) * sCb + (z % hdiv) * sCh;
    const int m0 = blockIdx.x * 128;
    const int n0 = blockIdx.y * BN;

    // ldmatrix smem offsets (stage-relative)
    uint32_t offA[4][2], offB[NA / 2][2];
    #pragma unroll
    for (int am = 0; am < 4; am++)
        #pragma unroll
        for (int kh = 0; kh < 2; kh++) {
            int mrow  = wm * 64 + am * 16 + (lane & 7) + ((lane >> 3) & 1) * 8;
            int chunk = kh * 2 + ((lane >> 4) & 1);
            offA[am][kh] = (uint32_t)(mrow * 64 + ((chunk ^ ((mrow >> 1) & 3)) << 4));
        }
    #pragma unroll
    for (int p = 0; p < NA / 2; p++)
        #pragma unroll
        for (int kh = 0; kh < 2; kh++) {
            int nrow  = wn * WN + p * 16 + (lane & 7) + ((lane >> 4) & 1) * 8;
            int chunk = kh * 2 + ((lane >> 3) & 1);
            offB[p][kh] = (uint32_t)(B_HI + nrow * 64 + ((chunk ^ ((nrow >> 1) & 3)) << 4));
        }

    float acc[4][NA][4];
    #pragma unroll
    for (int i = 0; i < 4; i++)
        #pragma unroll
        for (int j = 0; j < NA; j++)
            #pragma unroll
            for (int e = 0; e < 4; e++) acc[i][j][e] = 0.0f;

    float4 pa[4], pb[NB4];
    auto LOADG = [&](int k0) {
        #pragma unroll
        for (int i = 0; i < 4; i++) {
            int idx = i * 256 + tid, row = idx >> 3, k4 = idx & 7;
            pa[i] = *(const float4*)&A[(long)(m0 + row) * lda + k0 + k4 * 4];
        }
        #pragma unroll
        for (int i = 0; i < NB4; i++) {
            int idx = i * 256 + tid, row = idx >> 3, k4 = idx & 7;
            pb[i] = *(const float4*)&B[(long)(n0 + row) * ldb + k0 + k4 * 4];
        }
    };
    auto STORES = [&](uint32_t base) {
        #pragma unroll
        for (int i = 0; i < 4; i++) {
            int idx = i * 256 + tid, row = idx >> 3, k4 = idx & 7;
            split_store(base, base + A_LO, row, k4, pa[i]);
        }
        #pragma unroll
        for (int i = 0; i < NB4; i++) {
            int idx = i * 256 + tid, row = idx >> 3, k4 = idx & 7;
            split_store(base + B_HI, base + B_HI + BLO_D, row, k4, pb[i]);
        }
    };

    const int nk = K >> 5;
    LOADG(0);
    STORES(sb0);
    __syncthreads();

    for (int t = 0; t < nk; t++) {
        const uint32_t sb = sb0 + (uint32_t)(t & 1) * STAGE;
        if (t + 1 < nk) LOADG((t + 1) * 32);

        #pragma unroll
        for (int kh = 0; kh < 2; kh++) {
            uint32_t ah[4][4], al[4][4];
            #pragma unroll
            for (int am = 0; am < 4; am++) {
                ldm4(ah[am], sb + offA[am][kh]);
                ldm4(al[am], sb + offA[am][kh] + A_LO);
            }
            uint32_t bh[NA / 2][4], bl[NA / 2][4];
            #pragma unroll
            for (int p = 0; p < NA / 2; p++) {
                ldm4(bh[p], sb + offB[p][kh]);
                ldm4(bl[p], sb + offB[p][kh] + BLO_D);
            }
            #pragma unroll
            for (int am = 0; am < 4; am++)
                #pragma unroll
                for (int na = 0; na < NA; na++) {
                    const uint32_t* bhp = &bh[na >> 1][(na & 1) * 2];
                    const uint32_t* blp = &bl[na >> 1][(na & 1) * 2];
                    mma16816(acc[am][na], ah[am], bhp);
                    mma16816(acc[am][na], ah[am], blp);
                    mma16816(acc[am][na], al[am], bhp);
                }
        }

        if (t + 1 < nk) STORES(sb0 + (uint32_t)((t & 1) ^ 1) * STAGE);
        __syncthreads();
    }

    // epilogue: D frag lane l -> rows (l>>2), (l>>2)+8; cols (l&3)*2, +1
    #pragma unroll
    for (int am = 0; am < 4; am++)
        #pragma unroll
        for (int na = 0; na < NA; na++) {
            int row = m0 + wm * 64 + am * 16 + (lane >> 2);
            int col = n0 + wn * WN + na * 8 + (lane & 3) * 2;
            float* base0 = &C[(long)row * ldc + col];
            float* base1 = &C[(long)(row + 8) * ldc + col];
            float2 r0 = { alpha * acc[am][na][0], alpha * acc[am][na][1] };
            float2 r1 = { alpha * acc[am][na][2], alpha * acc[am][na][3] };
            if (ACCUM) {
                float2 o0 = *(float2*)base0, o1 = *(float2*)base1;
                r0.x += o0.x; r0.y += o0.y; r1.x += o1.x; r1.y += o1.y;
            }
            *(float2*)base0 = r0;
            *(float2*)base1 = r1;
        }
}

// ---------------- elementwise kernels ----------------
__global__ void embed_kernel(const int* __restrict__ tokens,
                             const float* __restrict__ embed,
                             float* __restrict__ h)
{
    int row = blockIdx.x;
    int tok = tokens[row];
    ((float4*)(h + (long)row * DIMN))[threadIdx.x] =
        ((const float4*)(embed + (long)tok * DIMN))[threadIdx.x];
}

__global__ void rmsnorm_kernel(const float* __restrict__ x,
                               const float* __restrict__ w,
                               float* __restrict__ out)
{
    int row = blockIdx.x;
    float4 v = ((const float4*)(x + (long)row * DIMN))[threadIdx.x];
    float ss = v.x*v.x + v.y*v.y + v.z*v.z + v.w*v.w;
    __shared__ float red[8];
    #pragma unroll
    for (int o = 16; o > 0; o >>= 1) ss += __shfl_xor_sync(0xFFFFFFFFu, ss, o);
    if ((threadIdx.x & 31) == 0) red[threadIdx.x >> 5] = ss;
    __syncthreads();
    if (threadIdx.x < 8) {
        float s = red[threadIdx.x];
        #pragma unroll
        for (int o = 4; o > 0; o >>= 1) s += __shfl_xor_sync(0xFFu, s, o);
        if (threadIdx.x == 0) red[0] = s;
    }
    __syncthreads();
    float scale = rsqrtf(red[0] * (1.0f / DIMN) + EPS);
    float4 wv = ((const float4*)w)[threadIdx.x];
    float4 o4 = { v.x*scale*wv.x, v.y*scale*wv.y, v.z*scale*wv.z, v.w*scale*wv.w };
    ((float4*)(out + (long)row * DIMN))[threadIdx.x] = o4;
}

__global__ void softmax_kernel(float* __restrict__ att)
{
    long row = blockIdx.x;
    float4* p = (float4*)(att + row * (long)SEQ);
    float4 v = p[threadIdx.x];
    __shared__ float red[8];
    float mx = fmaxf(fmaxf(v.x, v.y), fmaxf(v.z, v.w));
    #pragma unroll
    for (int o = 16; o > 0; o >>= 1) mx = fmaxf(mx, __shfl_xor_sync(0xFFFFFFFFu, mx, o));
    if ((threadIdx.x & 31) == 0) red[threadIdx.x >> 5] = mx;
    __syncthreads();
    if (threadIdx.x < 8) {
        float s = red[threadIdx.x];
        #pragma unroll
        for (int o = 4; o > 0; o >>= 1) s = fmaxf(s, __shfl_xor_sync(0xFFu, s, o));
        if (threadIdx.x == 0) red[0] = s;
    }
    __syncthreads();
    mx = red[0];
    __syncthreads();
    v.x = expf(v.x - mx); v.y = expf(v.y - mx);
    v.z = expf(v.z - mx); v.w = expf(v.w - mx);
    float sum = v.x + v.y + v.z + v.w;
    #pragma unroll
    for (int o = 16; o > 0; o >>= 1) sum += __shfl_xor_sync(0xFFFFFFFFu, sum, o);
    if ((threadIdx.x & 31) == 0) red[threadIdx.x >> 5] = sum;
    __syncthreads();
    if (threadIdx.x < 8) {
        float s = red[threadIdx.x];
        #pragma unroll
        for (int o = 4; o > 0; o >>= 1) s += __shfl_xor_sync(0xFFu, s, o);
        if (threadIdx.x == 0) red[0] = s;
    }
    __syncthreads();
    float inv = 1.0f / red[0];
    v.x *= inv; v.y *= inv; v.z *= inv; v.w *= inv;
    p[threadIdx.x] = v;
}

__global__ void silu_mul_kernel(float4* __restrict__ g, const float4* __restrict__ u)
{
    long i = (long)blockIdx.x * blockDim.x + threadIdx.x;
    float4 gv = g[i], uv = u[i];
    gv.x = gv.x / (1.0f + expf(-gv.x)) * uv.x;
    gv.y = gv.y / (1.0f + expf(-gv.y)) * uv.y;
    gv.z = gv.z / (1.0f + expf(-gv.z)) * uv.z;
    gv.w = gv.w / (1.0f + expf(-gv.w)) * uv.w;
    g[i] = gv;
}

// vt[(b*H+h)][d][s] = v[b*SEQ+s][h*64+d]
__global__ void transpose_v_kernel(const float* __restrict__ v, float* __restrict__ vt)
{
    __shared__ float t[32][33];
    int bh = blockIdx.z, b = bh >> 4, hh = bh & 15;
    int s0 = blockIdx.x * 32, d0 = blockIdx.y * 32;
    int tx = threadIdx.x, ty = threadIdx.y;    // 32 x 8
    #pragma unroll
    for (int j = 0; j < 32; j += 8)
        t[ty + j][tx] = v[(long)(b * SEQ + s0 + ty + j) * DIMN + hh * HEAD_DIM + d0 + tx];
    __syncthreads();
    #pragma unroll
    for (int j = 0; j < 32; j += 8)
        vt[((long)bh * HEAD_DIM + d0 + ty + j) * SEQ + s0 + tx] = t[tx][ty + j];
}

// ---------------- launcher ----------------
extern "C" void kernel_launch(void* const* d_in, const int* in_sizes, int n_in,
                              void* d_out, int out_size)
{
    const int*   tokens  = (const int*)  d_in[0];
    const float* embed   = (const float*)d_in[1];
    const float* Wq      = (const float*)d_in[2];
    const float* Wk      = (const float*)d_in[3];
    const float* Wv      = (const float*)d_in[4];
    const float* Wo      = (const float*)d_in[5];
    const float* Wg      = (const float*)d_in[6];
    const float* Wu      = (const float*)d_in[7];
    const float* Wd      = (const float*)d_in[8];
    const float* ln1     = (const float*)d_in[9];
    const float* ln2     = (const float*)d_in[10];
    const float* norm_w  = (const float*)d_in[11];
    const float* lm_head = (const float*)d_in[12];
    float* out = (float*)d_out;

    float *h, *x, *q, *k, *v, *vt, *y, *att, *gate, *up;
    cudaGetSymbolAddress((void**)&h,    g_h);
    cudaGetSymbolAddress((void**)&x,    g_x);
    cudaGetSymbolAddress((void**)&q,    g_q);
    cudaGetSymbolAddress((void**)&k,    g_k);
    cudaGetSymbolAddress((void**)&v,    g_v);
    cudaGetSymbolAddress((void**)&vt,   g_vt);
    cudaGetSymbolAddress((void**)&y,    g_y);
    cudaGetSymbolAddress((void**)&att,  g_att);
    cudaGetSymbolAddress((void**)&gate, g_gate);
    cudaGetSymbolAddress((void**)&up,   g_up);

    const int DYN128 = 2 * (16384 + 128 * 128);   // 65536
    const int DYN64  = 2 * (16384 + 64 * 128);    // 49152
    cudaFuncSetAttribute(mma_gemm<128, false>, cudaFuncAttributeMaxDynamicSharedMemorySize, DYN128);
    cudaFuncSetAttribute(mma_gemm<128, true>,  cudaFuncAttributeMaxDynamicSharedMemorySize, DYN128);
    cudaFuncSetAttribute(mma_gemm<64,  false>, cudaFuncAttributeMaxDynamicSharedMemorySize, DYN64);

    const float scale = 1.0f / sqrtf((float)HEAD_DIM);

    embed_kernel<<<MTOK, 256>>>(tokens, embed, h);

    // grid: x = m-tiles (fast -> B-panel reuse in L2 across a wave), y = n-tiles
    dim3 gProj (MTOK / 128, DIMN / 128, 1);            // 16 x 8
    dim3 gFfn  (MTOK / 128, HIDDEN / 128, 1);          // 16 x 32
    dim3 gScore(SEQ / 128, SEQ / 128, BATCH * HEADS);  // 8 x 8 x 32
    dim3 gAV   (SEQ / 128, 1, BATCH * HEADS);          // 8 x 1 x 32
    dim3 gHead (MTOK / 128, VOCAB / 128, 1);           // 16 x 250
    dim3 gTr   (SEQ / 32, HEAD_DIM / 32, BATCH * HEADS);

    for (int l = 0; l < LAYERS; l++) {
        const float* wq = Wq + (long)l * DIMN * DIMN;
        const float* wk = Wk + (long)l * DIMN * DIMN;
        const float* wv = Wv + (long)l * DIMN * DIMN;
        const float* wo = Wo + (long)l * DIMN * DIMN;
        const float* wg = Wg + (long)l * HIDDEN * DIMN;
        const float* wu = Wu + (long)l * HIDDEN * DIMN;
        const float* wd = Wd + (long)l * DIMN * HIDDEN;

        rmsnorm_kernel<<<MTOK, 256>>>(h, ln1 + (long)l * DIMN, x);

        mma_gemm<128, false><<<gProj, 256, DYN128>>>(x, DIMN, 0, 0, wq, DIMN, 0, 0,
                                                     q, DIMN, 0, 0, DIMN, 1.0f, 1);
        mma_gemm<128, false><<<gProj, 256, DYN128>>>(x, DIMN, 0, 0, wk, DIMN, 0, 0,
                                                     k, DIMN, 0, 0, DIMN, 1.0f, 1);
        mma_gemm<128, false><<<gProj, 256, DYN128>>>(x, DIMN, 0, 0, wv, DIMN, 0, 0,
                                                     v, DIMN, 0, 0, DIMN, 1.0f, 1);

        // att = scale * q k^T  (batched over b,h; K = HEAD_DIM)
        mma_gemm<128, false><<<gScore, 256, DYN128>>>(
            q, DIMN, (long)SEQ * DIMN, HEAD_DIM,
            k, DIMN, (long)SEQ * DIMN, HEAD_DIM,
            att, SEQ, (long)HEADS * SEQ * SEQ, (long)SEQ * SEQ,
            HEAD_DIM, scale, HEADS);

        softmax_kernel<<<BATCH * HEADS * SEQ, 256>>>(att);

        transpose_v_kernel<<<gTr, dim3(32, 8)>>>(v, vt);

        // y = att @ v  (NT with vt[b,h][d][s]; N = HEAD_DIM, K = SEQ)
        mma_gemm<64, false><<<gAV, 256, DYN64>>>(
            att, SEQ, (long)HEADS * SEQ * SEQ, (long)SEQ * SEQ,
            vt, SEQ, (long)HEADS * HEAD_DIM * SEQ, (long)HEAD_DIM * SEQ,
            y, DIMN, (long)SEQ * DIMN, HEAD_DIM,
            SEQ, 1.0f, HEADS);

        // h += y @ Wo^T
        mma_gemm<128, true><<<gProj, 256, DYN128>>>(y, DIMN, 0, 0, wo, DIMN, 0, 0,
                                                    h, DIMN, 0, 0, DIMN, 1.0f, 1);

        rmsnorm_kernel<<<MTOK, 256>>>(h, ln2 + (long)l * DIMN, x);

        mma_gemm<128, false><<<gFfn, 256, DYN128>>>(x, DIMN, 0, 0, wg, DIMN, 0, 0,
                                                    gate, HIDDEN, 0, 0, DIMN, 1.0f, 1);
        mma_gemm<128, false><<<gFfn, 256, DYN128>>>(x, DIMN, 0, 0, wu, DIMN, 0, 0,
                                                    up, HIDDEN, 0, 0, DIMN, 1.0f, 1);

        silu_mul_kernel<<<(MTOK * (long)HIDDEN / 4) / 256, 256>>>((float4*)gate, (const float4*)up);

        // h += gate @ Wd^T
        mma_gemm<128, true><<<gProj, 256, DYN128>>>(gate, HIDDEN, 0, 0, wd, HIDDEN, 0, 0,
                                                    h, DIMN, 0, 0, HIDDEN, 1.0f, 1);
    }

    rmsnorm_kernel<<<MTOK, 256>>>(h, norm_w, x);
    mma_gemm<128, false><<<gHead, 256, DYN128>>>(x, DIMN, 0, 0, lm_head, DIMN, 0, 0,
                                                 out, VOCAB, 0, 0, DIMN, 1.0f, 1);
}